// round 13
// baseline (speedup 1.0000x reference)
#include <cuda_runtime.h>
#include <cstdint>

// LightGCN aggregation (COO SpMM, DIM=32):
//   out[r] = sum_{e: rows[e]==r} vals[e] * x[cols[e]]
//
// Pipeline (2 graph nodes):
//   1) bucket_scatter: pos = atomicAdd(cnt[row]); edges[row*72+pos]=(val,col)
//   2) seg_reduce: warp = 4 rows processed JOINTLY (all 4 octets on one row
//      at a time, octet o takes edge pair {2o,2o+1}, stride 8) -> warp time
//      ~ sum(cnt_r/8) instead of max(cnt_r/4): kills the E[max of 4
//      Poisson(16)]/mean = 1.34x imbalance of the static octet-per-row map.
//      Cross-octet shfl reduce per row; octet 0 stores the 128B row.
//      cnt re-zeroed in the EPILOGUE (after all loads) -> no memset node.

static constexpr int DIM  = 32;
static constexpr int QPE  = DIM / 4;
static constexpr int MAXN = 131072;     // > 100,000 nodes
static constexpr int MAXE = 1700000;    // fallback threshold
static constexpr int CAP  = 64;         // usable bucket capacity (mean deg 16)
static constexpr int STRIDE = 72;       // slots per bucket (576B, 16B-aligned)
static constexpr int TPB  = 256;

// ---- scratch (static device globals, zero-initialized at module load) ----
__device__ int                d_cnt[MAXN];
__device__ unsigned long long d_edges[(size_t)MAXN * STRIDE];  // ~75MB

// ========================= kernel 1: bucket scatter =========================
// 8 edges per thread: two int4/float4 loads per array, 8 independent
// atomic->store chains in flight.
__global__ void __launch_bounds__(TPB)
bucket_scatter_kernel(const int4*   __restrict__ rows4,
                      const int4*   __restrict__ cols4,
                      const float4* __restrict__ vals4,
                      int n_edges)
{
    int idx = blockIdx.x * TPB + threadIdx.x;
    int ng8 = n_edges >> 3;                 // groups of 8 edges
    if (idx < ng8) {
        int g0 = idx * 2, g1 = idx * 2 + 1;
        int4   ra4 = __ldg(&rows4[g0]);
        int4   rb4 = __ldg(&rows4[g1]);
        int4   ca4 = __ldg(&cols4[g0]);
        int4   cb4 = __ldg(&cols4[g1]);
        float4 va4 = __ldg(&vals4[g0]);
        float4 vb4 = __ldg(&vals4[g1]);

        int   ra[8] = { ra4.x, ra4.y, ra4.z, ra4.w, rb4.x, rb4.y, rb4.z, rb4.w };
        int   ca[8] = { ca4.x, ca4.y, ca4.z, ca4.w, cb4.x, cb4.y, cb4.z, cb4.w };
        float va[8] = { va4.x, va4.y, va4.z, va4.w, vb4.x, vb4.y, vb4.z, vb4.w };

        int pos[8];
        #pragma unroll
        for (int i = 0; i < 8; i++)
            pos[i] = atomicAdd(&d_cnt[ra[i]], 1);
        #pragma unroll
        for (int i = 0; i < 8; i++)
            if (pos[i] < CAP)
                d_edges[(size_t)ra[i] * STRIDE + pos[i]] =
                    ((unsigned long long)__float_as_uint(va[i]) << 32)
                    | (unsigned int)ca[i];
    } else if (idx == ng8) {                 // scalar tail (n_edges % 8)
        const int*   rows = (const int*)  rows4;
        const int*   cols = (const int*)  cols4;
        const float* vals = (const float*)vals4;
        for (int e = ng8 * 8; e < n_edges; e++) {
            int pos = atomicAdd(&d_cnt[rows[e]], 1);
            if (pos < CAP)
                d_edges[(size_t)rows[e] * STRIDE + pos] =
                    ((unsigned long long)__float_as_uint(vals[e]) << 32)
                    | (unsigned int)cols[e];
        }
    }
}

// ========================= kernel 2: segment reduce =========================
// warp = 4 rows, processed sequentially with the WHOLE warp per row.
// lanes: q = lane&7 (float4 quarter), o = lane>>3 (octet 0..3).
// Row loop: octet o covers edge pairs {2o, 2o+1} + 8k  (one 16B ull2 load,
// broadcast across the octet's 8 lanes; two gather chains per thread).
// Per row: shfl_xor(8,16) folds the 4 octets; octet 0 stores 128B.
// Per-warp time ~ sum(ceil(cnt_r/8)) -- balanced across warps.
__global__ void __launch_bounds__(TPB)
seg_reduce_kernel(const float4* __restrict__ x4,   // [n_nodes * 8]
                  float4*       __restrict__ out4, // [n_nodes * 8]
                  int n_nodes)
{
    int tid  = blockIdx.x * TPB + threadIdx.x;
    int warp = tid >> 5;
    int lane = threadIdx.x & 31;
    int q    = lane & 7;
    int o    = lane >> 3;

    int base = warp * 4;
    if (base >= n_nodes) return;

    // all 4 row counts in one 16B load (d_cnt is 16B aligned, base % 4 == 0)
    int4 c4 = __ldg(&((const int4*)d_cnt)[warp]);
    int cnts[4] = { c4.x, c4.y, c4.z, c4.w };

    #pragma unroll
    for (int r = 0; r < 4; r++) {
        int row = base + r;
        if (row >= n_nodes) break;
        int cnt = min(cnts[r], CAP);

        const unsigned long long* seg  = d_edges + (size_t)row * STRIDE;
        const ulonglong2*         seg2 = (const ulonglong2*)seg;

        float4 a = make_float4(0.f, 0.f, 0.f, 0.f);

        int i = o * 2;
        for (; i + 1 < cnt; i += 8) {
            ulonglong2 p = __ldg(&seg2[i >> 1]);
            int   c0 = (int)(unsigned int)p.x;
            int   c1 = (int)(unsigned int)p.y;
            float v0 = __uint_as_float((unsigned int)(p.x >> 32));
            float v1 = __uint_as_float((unsigned int)(p.y >> 32));
            float4 xv0 = __ldg(&x4[c0 * QPE + q]);
            float4 xv1 = __ldg(&x4[c1 * QPE + q]);
            a.x += v0 * xv0.x;  a.y += v0 * xv0.y;
            a.z += v0 * xv0.z;  a.w += v0 * xv0.w;
            a.x += v1 * xv1.x;  a.y += v1 * xv1.y;
            a.z += v1 * xv1.z;  a.w += v1 * xv1.w;
        }
        if (i < cnt) {                        // odd leftover edge for this octet
            unsigned long long p = __ldg(&seg[i]);
            int   c = (int)(unsigned int)p;
            float v = __uint_as_float((unsigned int)(p >> 32));
            float4 xv = __ldg(&x4[c * QPE + q]);
            a.x += v * xv.x;  a.y += v * xv.y;
            a.z += v * xv.z;  a.w += v * xv.w;
        }

        // fold the 4 octets (lanes q, q+8, q+16, q+24)
        #pragma unroll
        for (int m = 8; m <= 16; m <<= 1) {
            a.x += __shfl_xor_sync(0xffffffffu, a.x, m);
            a.y += __shfl_xor_sync(0xffffffffu, a.y, m);
            a.z += __shfl_xor_sync(0xffffffffu, a.z, m);
            a.w += __shfl_xor_sync(0xffffffffu, a.w, m);
        }

        if (o == 0)
            out4[row * QPE + q] = a;
    }

    // epilogue: restore replay invariant (AFTER all reads/stores; the R10
    // poison was a store *before* the load loop, not after)
    if (lane < 4 && base + lane < n_nodes)
        d_cnt[base + lane] = 0;
}

// ===================== fallback: one-pass RED (oversize) ====================
__device__ __forceinline__ void red_add_v4(float* dst, float4 m) {
    asm volatile("red.global.add.v4.f32 [%0], {%1, %2, %3, %4};"
                 :: "l"(dst), "f"(m.x), "f"(m.y), "f"(m.z), "f"(m.w) : "memory");
}

__global__ void __launch_bounds__(TPB)
coo_red_kernel(const int* __restrict__ rows, const int* __restrict__ cols,
               const float* __restrict__ vals, const float4* __restrict__ x4,
               float* __restrict__ out, int n_edges)
{
    int idx = blockIdx.x * TPB + threadIdx.x;
    if (idx >= n_edges * QPE) return;
    int e = idx >> 3, q = idx & 7;
    int   r = rows[e], c = cols[e];
    float v = vals[e];
    float4 xv = __ldg(&x4[c * QPE + q]);
    float4 m = make_float4(xv.x * v, xv.y * v, xv.z * v, xv.w * v);
    red_add_v4(out + ((size_t)r * DIM + q * 4), m);
}

// ================================ launch ====================================
extern "C" void kernel_launch(void* const* d_in, const int* in_sizes, int n_in,
                              void* d_out, int out_size)
{
    const int*    rows = (const int*)   d_in[0];
    const int*    cols = (const int*)   d_in[1];
    const float*  vals = (const float*) d_in[2];
    const float4* x4   = (const float4*)d_in[3];

    int n_edges = in_sizes[0];
    int n_nodes = out_size / DIM;

    if (n_nodes > MAXN || n_edges > MAXE) {
        // oversize safety net: one-pass RED kernel
        cudaMemsetAsync(d_out, 0, (size_t)out_size * sizeof(float), 0);
        int total = n_edges * QPE;
        coo_red_kernel<<<(total + TPB - 1) / TPB, TPB>>>(
            rows, cols, vals, x4, (float*)d_out, n_edges);
        return;
    }

    int ng8      = n_edges >> 3;
    int e_blocks = (ng8 + 1 + TPB - 1) / TPB;   // +1 thread for tail

    // counts are zero on entry (zero-init at load; reduce epilogue re-zeroes)
    bucket_scatter_kernel<<<e_blocks, TPB>>>(
        (const int4*)rows, (const int4*)cols, (const float4*)vals, n_edges);

    // one warp per 4 rows
    int n_warps   = (n_nodes + 3) / 4;
    int n_threads = n_warps * 32;
    int n_blocks  = (n_threads + TPB - 1) / TPB;
    seg_reduce_kernel<<<n_blocks, TPB>>>(x4, (float4*)d_out, n_nodes);
}

// round 14
// speedup vs baseline: 1.0308x; 1.0308x over previous
#include <cuda_runtime.h>
#include <cstdint>

// LightGCN aggregation (COO SpMM, DIM=32):
//   out[r] = sum_{e: rows[e]==r} vals[e] * x[cols[e]]
//
// Pipeline (2 graph nodes):
//   1) bucket_scatter: pos = atomicAdd(cnt[row]); edges[row*48+pos]=(val,col)
//   2) seg_reduce: warp = 4 rows, octet per row (R12 shape), pure-read body,
//      SOFTWARE-PIPELINED edge packets (prefetch iter k+1 before k's gathers),
//      epilogue re-zeroes cnt (replay invariant, no memset node).
//
// R13 lessons: (a) joint-row balancing cost more instructions than the
// imbalance it saved -> reverted. (b) Real binder of the 27us reduce:
// STRIDE=72 buckets = 75MB >> L2 share -> edge reads miss to DRAM (34MB
// observed) and serialize ahead of gathers. STRIDE=48 -> 38.4MB, resident.

static constexpr int DIM  = 32;
static constexpr int QPE  = DIM / 4;
static constexpr int MAXN = 131072;     // > 100,000 nodes
static constexpr int MAXE = 1700000;    // fallback threshold
static constexpr int CAP  = 48;         // Poisson(16): P(max over 1e5 >= 48) ~ 1e-10
static constexpr int STRIDE = 48;       // 384B per bucket, 16B-aligned
static constexpr int TPB  = 256;

// ---- scratch (static device globals, zero-initialized at module load) ----
__device__ int                d_cnt[MAXN];
__device__ unsigned long long d_edges[(size_t)MAXN * STRIDE];  // 38.4MB used

// ========================= kernel 1: bucket scatter =========================
// 4 edges per thread (one int4/float4 load per array); atomics issued as a
// batch of 4 independent chains before the dependent stores.
__global__ void __launch_bounds__(TPB)
bucket_scatter_kernel(const int4*   __restrict__ rows4,
                      const int4*   __restrict__ cols4,
                      const float4* __restrict__ vals4,
                      int n_edges)
{
    int idx = blockIdx.x * TPB + threadIdx.x;
    int ng  = n_edges >> 2;
    if (idx < ng) {
        int4   r = __ldg(&rows4[idx]);
        int4   c = __ldg(&cols4[idx]);
        float4 v = __ldg(&vals4[idx]);

        int   ra[4] = { r.x, r.y, r.z, r.w };
        int   ca[4] = { c.x, c.y, c.z, c.w };
        float va[4] = { v.x, v.y, v.z, v.w };

        int pos[4];
        #pragma unroll
        for (int i = 0; i < 4; i++)
            pos[i] = atomicAdd(&d_cnt[ra[i]], 1);
        #pragma unroll
        for (int i = 0; i < 4; i++)
            if (pos[i] < CAP)
                d_edges[(size_t)ra[i] * STRIDE + pos[i]] =
                    ((unsigned long long)__float_as_uint(va[i]) << 32)
                    | (unsigned int)ca[i];
    } else if (idx == ng) {                  // scalar tail (n_edges % 4)
        const int*   rows = (const int*)  rows4;
        const int*   cols = (const int*)  cols4;
        const float* vals = (const float*)vals4;
        for (int e = ng * 4; e < n_edges; e++) {
            int pos = atomicAdd(&d_cnt[rows[e]], 1);
            if (pos < CAP)
                d_edges[(size_t)rows[e] * STRIDE + pos] =
                    ((unsigned long long)__float_as_uint(vals[e]) << 32)
                    | (unsigned int)cols[e];
        }
    }
}

// ========================= kernel 2: segment reduce =========================
// warp = 4 consecutive rows; octet (8 lanes) per row; lane q = float4 quarter.
// Pure-read body; 4 edges/iter via two ull2 packet loads, with the NEXT
// iteration's packets prefetched before this iteration's gathers so the
// edge-load latency hides under the gather chain. Epilogue zeroes d_cnt.
__global__ void __launch_bounds__(TPB, 6)
seg_reduce_kernel(const float4* __restrict__ x4,   // [n_nodes * 8]
                  float4*       __restrict__ out4, // [n_nodes * 8]
                  int n_nodes)
{
    int tid  = blockIdx.x * TPB + threadIdx.x;
    int warp = tid >> 5;
    int lane = threadIdx.x & 31;
    int q    = lane & 7;
    int sub  = lane >> 3;

    int base = warp * 4;
    int row  = base + sub;
    if (row >= n_nodes) return;

    int cnt = min(__ldg(&d_cnt[row]), CAP);

    const unsigned long long* seg  = d_edges + (size_t)row * STRIDE;
    const ulonglong2*         seg2 = (const ulonglong2*)seg;   // 16B aligned

    float4 a0 = make_float4(0.f, 0.f, 0.f, 0.f);
    float4 a1 = make_float4(0.f, 0.f, 0.f, 0.f);

    int i = 0;
    ulonglong2 pa, pb;
    if (i + 3 < cnt) {
        pa = __ldg(&seg2[0]);
        pb = __ldg(&seg2[1]);
    }
    while (i + 3 < cnt) {
        int ni = i + 4;
        ulonglong2 na, nb;
        if (ni + 3 < cnt) {                  // prefetch next packet pair
            na = __ldg(&seg2[(ni >> 1)]);
            nb = __ldg(&seg2[(ni >> 1) + 1]);
        }

        int   c0 = (int)(unsigned int)pa.x;
        int   c1 = (int)(unsigned int)pa.y;
        int   c2 = (int)(unsigned int)pb.x;
        int   c3 = (int)(unsigned int)pb.y;
        float v0 = __uint_as_float((unsigned int)(pa.x >> 32));
        float v1 = __uint_as_float((unsigned int)(pa.y >> 32));
        float v2 = __uint_as_float((unsigned int)(pb.x >> 32));
        float v3 = __uint_as_float((unsigned int)(pb.y >> 32));

        float4 x0 = __ldg(&x4[c0 * QPE + q]);
        float4 x1 = __ldg(&x4[c1 * QPE + q]);
        float4 x2 = __ldg(&x4[c2 * QPE + q]);
        float4 x3 = __ldg(&x4[c3 * QPE + q]);

        a0.x += v0 * x0.x;  a0.y += v0 * x0.y;
        a0.z += v0 * x0.z;  a0.w += v0 * x0.w;
        a1.x += v1 * x1.x;  a1.y += v1 * x1.y;
        a1.z += v1 * x1.z;  a1.w += v1 * x1.w;
        a0.x += v2 * x2.x;  a0.y += v2 * x2.y;
        a0.z += v2 * x2.z;  a0.w += v2 * x2.w;
        a1.x += v3 * x3.x;  a1.y += v3 * x3.y;
        a1.z += v3 * x3.z;  a1.w += v3 * x3.w;

        pa = na; pb = nb; i = ni;
    }
    for (; i < cnt; i++) {                    // <=3 scalar tail edges
        unsigned long long p = __ldg(&seg[i]);
        int   c = (int)(unsigned int)p;
        float v = __uint_as_float((unsigned int)(p >> 32));
        float4 xv = __ldg(&x4[c * QPE + q]);
        a0.x += v * xv.x;  a0.y += v * xv.y;
        a0.z += v * xv.z;  a0.w += v * xv.w;
    }

    float4 acc;
    acc.x = a0.x + a1.x;
    acc.y = a0.y + a1.y;
    acc.z = a0.z + a1.z;
    acc.w = a0.w + a1.w;

    out4[row * QPE + q] = acc;

    // epilogue: restore replay invariant (store AFTER all loads in program
    // order; each row zeroed exactly once by its owning warp)
    if (lane < 4 && base + lane < n_nodes)
        d_cnt[base + lane] = 0;
}

// ===================== fallback: one-pass RED (oversize) ====================
__device__ __forceinline__ void red_add_v4(float* dst, float4 m) {
    asm volatile("red.global.add.v4.f32 [%0], {%1, %2, %3, %4};"
                 :: "l"(dst), "f"(m.x), "f"(m.y), "f"(m.z), "f"(m.w) : "memory");
}

__global__ void __launch_bounds__(TPB)
coo_red_kernel(const int* __restrict__ rows, const int* __restrict__ cols,
               const float* __restrict__ vals, const float4* __restrict__ x4,
               float* __restrict__ out, int n_edges)
{
    int idx = blockIdx.x * TPB + threadIdx.x;
    if (idx >= n_edges * QPE) return;
    int e = idx >> 3, q = idx & 7;
    int   r = rows[e], c = cols[e];
    float v = vals[e];
    float4 xv = __ldg(&x4[c * QPE + q]);
    float4 m = make_float4(xv.x * v, xv.y * v, xv.z * v, xv.w * v);
    red_add_v4(out + ((size_t)r * DIM + q * 4), m);
}

// ================================ launch ====================================
extern "C" void kernel_launch(void* const* d_in, const int* in_sizes, int n_in,
                              void* d_out, int out_size)
{
    const int*    rows = (const int*)   d_in[0];
    const int*    cols = (const int*)   d_in[1];
    const float*  vals = (const float*) d_in[2];
    const float4* x4   = (const float4*)d_in[3];

    int n_edges = in_sizes[0];
    int n_nodes = out_size / DIM;

    if (n_nodes > MAXN || n_edges > MAXE) {
        // oversize safety net: one-pass RED kernel
        cudaMemsetAsync(d_out, 0, (size_t)out_size * sizeof(float), 0);
        int total = n_edges * QPE;
        coo_red_kernel<<<(total + TPB - 1) / TPB, TPB>>>(
            rows, cols, vals, x4, (float*)d_out, n_edges);
        return;
    }

    int ng       = n_edges >> 2;
    int e_blocks = (ng + 1 + TPB - 1) / TPB;   // +1 thread for tail

    // counts are zero on entry (zero-init at load; reduce epilogue re-zeroes)
    bucket_scatter_kernel<<<e_blocks, TPB>>>(
        (const int4*)rows, (const int4*)cols, (const float4*)vals, n_edges);

    // one warp per 4 rows
    int n_warps   = (n_nodes + 3) / 4;
    int n_threads = n_warps * 32;
    int n_blocks  = (n_threads + TPB - 1) / TPB;
    seg_reduce_kernel<<<n_blocks, TPB>>>(x4, (float4*)d_out, n_nodes);
}

// round 15
// speedup vs baseline: 1.0829x; 1.0506x over previous
#include <cuda_runtime.h>
#include <cstdint>

// LightGCN aggregation (COO SpMM, DIM=32):
//   out[r] = sum_{e: rows[e]==r} vals[e] * x[cols[e]]
//
// Pipeline (2 graph nodes):
//   1) bucket_scatter (R9 form): 4 edges/thread, int4 loads, batched atomics,
//      guarded stores into fixed 48-slot row buckets.
//   2) seg_reduce (R12-exact body): warp = 4 rows, octet per row, pure-read,
//      4 edges/iter via two ull2 loads, dual accumulators, 32 regs, no
//      launch_bounds extras, no software pipeline (R14 showed both hurt).
//      Epilogue zeroes d_cnt -> no memset node.
//
// Wall model: reduce sits on the L1tex wavefront wall (~4.5 sectors/edge ->
// ~25us floor); scatter on the LSU/LTS lane wall (~13us). This round strips
// everything that isn't required to sit on those walls.

static constexpr int DIM  = 32;
static constexpr int QPE  = DIM / 4;
static constexpr int MAXN = 131072;     // > 100,000 nodes
static constexpr int MAXE = 1700000;    // fallback threshold
static constexpr int CAP  = 48;         // Poisson(16): P(max over 1e5 >= 48) ~ 1e-10
static constexpr int STRIDE = 48;       // 384B per bucket, 16B-aligned
static constexpr int TPB  = 256;

// ---- scratch (static device globals, zero-initialized at module load) ----
__device__ int                d_cnt[MAXN];
__device__ unsigned long long d_edges[(size_t)MAXN * STRIDE];  // 38.4MB used

// ========================= kernel 1: bucket scatter =========================
__global__ void __launch_bounds__(TPB)
bucket_scatter_kernel(const int4*   __restrict__ rows4,
                      const int4*   __restrict__ cols4,
                      const float4* __restrict__ vals4,
                      int n_edges)
{
    int idx = blockIdx.x * TPB + threadIdx.x;
    int ng  = n_edges >> 2;
    if (idx < ng) {
        int4   r = __ldg(&rows4[idx]);
        int4   c = __ldg(&cols4[idx]);
        float4 v = __ldg(&vals4[idx]);

        int   ra[4] = { r.x, r.y, r.z, r.w };
        int   ca[4] = { c.x, c.y, c.z, c.w };
        float va[4] = { v.x, v.y, v.z, v.w };

        int pos[4];
        #pragma unroll
        for (int i = 0; i < 4; i++)
            pos[i] = atomicAdd(&d_cnt[ra[i]], 1);
        #pragma unroll
        for (int i = 0; i < 4; i++)
            if (pos[i] < CAP)
                d_edges[(size_t)ra[i] * STRIDE + pos[i]] =
                    ((unsigned long long)__float_as_uint(va[i]) << 32)
                    | (unsigned int)ca[i];
    } else if (idx == ng) {                  // scalar tail (n_edges % 4)
        const int*   rows = (const int*)  rows4;
        const int*   cols = (const int*)  cols4;
        const float* vals = (const float*)vals4;
        for (int e = ng * 4; e < n_edges; e++) {
            int pos = atomicAdd(&d_cnt[rows[e]], 1);
            if (pos < CAP)
                d_edges[(size_t)rows[e] * STRIDE + pos] =
                    ((unsigned long long)__float_as_uint(vals[e]) << 32)
                    | (unsigned int)cols[e];
        }
    }
}

// ========================= kernel 2: segment reduce =========================
// R12-exact body: warp = 4 consecutive rows; octet (8 lanes) per row;
// lane q = float4 quarter. Pure reads (cnt via __ldg); 4 edges/iter via two
// ulonglong2 packet loads -> 4 gather chains per thread; dual accumulators.
// Epilogue zeroes d_cnt (store strictly after all loads in program order).
__global__ void __launch_bounds__(TPB)
seg_reduce_kernel(const float4* __restrict__ x4,   // [n_nodes * 8]
                  float4*       __restrict__ out4, // [n_nodes * 8]
                  int n_nodes)
{
    int tid  = blockIdx.x * TPB + threadIdx.x;
    int warp = tid >> 5;
    int lane = threadIdx.x & 31;
    int q    = lane & 7;
    int sub  = lane >> 3;

    int base = warp * 4;
    int row  = base + sub;
    if (row >= n_nodes) return;

    int cnt = min(__ldg(&d_cnt[row]), CAP);

    const unsigned long long* seg  = d_edges + (size_t)row * STRIDE;
    const ulonglong2*         seg2 = (const ulonglong2*)seg;   // 16B aligned

    float4 a0 = make_float4(0.f, 0.f, 0.f, 0.f);
    float4 a1 = make_float4(0.f, 0.f, 0.f, 0.f);

    int i = 0;
    for (; i + 3 < cnt; i += 4) {
        ulonglong2 pa = __ldg(&seg2[(i >> 1)]);
        ulonglong2 pb = __ldg(&seg2[(i >> 1) + 1]);

        int   c0 = (int)(unsigned int)pa.x;
        int   c1 = (int)(unsigned int)pa.y;
        int   c2 = (int)(unsigned int)pb.x;
        int   c3 = (int)(unsigned int)pb.y;
        float v0 = __uint_as_float((unsigned int)(pa.x >> 32));
        float v1 = __uint_as_float((unsigned int)(pa.y >> 32));
        float v2 = __uint_as_float((unsigned int)(pb.x >> 32));
        float v3 = __uint_as_float((unsigned int)(pb.y >> 32));

        float4 x0 = __ldg(&x4[c0 * QPE + q]);
        float4 x1 = __ldg(&x4[c1 * QPE + q]);
        float4 x2 = __ldg(&x4[c2 * QPE + q]);
        float4 x3 = __ldg(&x4[c3 * QPE + q]);

        a0.x += v0 * x0.x;  a0.y += v0 * x0.y;
        a0.z += v0 * x0.z;  a0.w += v0 * x0.w;
        a1.x += v1 * x1.x;  a1.y += v1 * x1.y;
        a1.z += v1 * x1.z;  a1.w += v1 * x1.w;
        a0.x += v2 * x2.x;  a0.y += v2 * x2.y;
        a0.z += v2 * x2.z;  a0.w += v2 * x2.w;
        a1.x += v3 * x3.x;  a1.y += v3 * x3.y;
        a1.z += v3 * x3.z;  a1.w += v3 * x3.w;
    }
    for (; i < cnt; i++) {                    // <=3 scalar tail edges
        unsigned long long p = __ldg(&seg[i]);
        int   c = (int)(unsigned int)p;
        float v = __uint_as_float((unsigned int)(p >> 32));
        float4 xv = __ldg(&x4[c * QPE + q]);
        a0.x += v * xv.x;  a0.y += v * xv.y;
        a0.z += v * xv.z;  a0.w += v * xv.w;
    }

    float4 acc;
    acc.x = a0.x + a1.x;
    acc.y = a0.y + a1.y;
    acc.z = a0.z + a1.z;
    acc.w = a0.w + a1.w;

    out4[row * QPE + q] = acc;

    // epilogue: restore replay invariant (each row zeroed by its owning warp)
    if (lane < 4 && base + lane < n_nodes)
        d_cnt[base + lane] = 0;
}

// ===================== fallback: one-pass RED (oversize) ====================
__device__ __forceinline__ void red_add_v4(float* dst, float4 m) {
    asm volatile("red.global.add.v4.f32 [%0], {%1, %2, %3, %4};"
                 :: "l"(dst), "f"(m.x), "f"(m.y), "f"(m.z), "f"(m.w) : "memory");
}

__global__ void __launch_bounds__(TPB)
coo_red_kernel(const int* __restrict__ rows, const int* __restrict__ cols,
               const float* __restrict__ vals, const float4* __restrict__ x4,
               float* __restrict__ out, int n_edges)
{
    int idx = blockIdx.x * TPB + threadIdx.x;
    if (idx >= n_edges * QPE) return;
    int e = idx >> 3, q = idx & 7;
    int   r = rows[e], c = cols[e];
    float v = vals[e];
    float4 xv = __ldg(&x4[c * QPE + q]);
    float4 m = make_float4(xv.x * v, xv.y * v, xv.z * v, xv.w * v);
    red_add_v4(out + ((size_t)r * DIM + q * 4), m);
}

// ================================ launch ====================================
extern "C" void kernel_launch(void* const* d_in, const int* in_sizes, int n_in,
                              void* d_out, int out_size)
{
    const int*    rows = (const int*)   d_in[0];
    const int*    cols = (const int*)   d_in[1];
    const float*  vals = (const float*) d_in[2];
    const float4* x4   = (const float4*)d_in[3];

    int n_edges = in_sizes[0];
    int n_nodes = out_size / DIM;

    if (n_nodes > MAXN || n_edges > MAXE) {
        // oversize safety net: one-pass RED kernel
        cudaMemsetAsync(d_out, 0, (size_t)out_size * sizeof(float), 0);
        int total = n_edges * QPE;
        coo_red_kernel<<<(total + TPB - 1) / TPB, TPB>>>(
            rows, cols, vals, x4, (float*)d_out, n_edges);
        return;
    }

    int ng       = n_edges >> 2;
    int e_blocks = (ng + 1 + TPB - 1) / TPB;   // +1 thread for tail

    // counts are zero on entry (zero-init at load; reduce epilogue re-zeroes)
    bucket_scatter_kernel<<<e_blocks, TPB>>>(
        (const int4*)rows, (const int4*)cols, (const float4*)vals, n_edges);

    // one warp per 4 rows
    int n_warps   = (n_nodes + 3) / 4;
    int n_threads = n_warps * 32;
    int n_blocks  = (n_threads + TPB - 1) / TPB;
    seg_reduce_kernel<<<n_blocks, TPB>>>(x4, (float4*)d_out, n_nodes);
}

// round 16
// speedup vs baseline: 1.1900x; 1.0988x over previous
#include <cuda_runtime.h>
#include <cstdint>

// COO SpMM: out[rows[e]] += vals[e] * x[cols[e]]   (DIM = 32)
//
// FINAL (champion config, measured 41.4us e2e / 39.3us kernel):
// one-pass gather + red.global.add.v4.f32 scatter.
//
// Layout: each warp covers 16 edges, 4 CONSECUTIVE edges per thread-octet.
//   lane: q = lane & 7 (float4 quarter of the 32-dim row), sub = lane >> 3
//   octet sub's edges: e = warpBase*16 + sub*4 + {0,1,2,3}
// Index/weight loads are one int4/int4/float4 per thread (16B aligned) ->
// 1 L1 request per scalar array per warp. Per edge, the x-gather and the
// RED scatter are each one contiguous 128B segment across the octet's 8
// lanes. RED is fire-and-forget (no latency exposure); the kernel sits on
// the LTS byte cap (~410MB visible RMW traffic).
//
// Session record: two-phase (bucket scatter + CSR-style reduce) bottomed at
// 45.5us (scatter 15 + reduce 26.6 walls, serialized); one-pass wall 39.3us
// reproduced 3x. One-pass wins.

static constexpr int DIM = 32;
static constexpr int QPE = DIM / 4;   // 8 float4 quarters per edge
static constexpr int TPB = 256;
static constexpr int EPT = 4;         // edges per thread
static constexpr int EPW = 16;        // edges per warp

__device__ __forceinline__ void red_add_v4(float* dst, float4 m) {
    asm volatile(
        "red.global.add.v4.f32 [%0], {%1, %2, %3, %4};"
        :: "l"(dst), "f"(m.x), "f"(m.y), "f"(m.z), "f"(m.w)
        : "memory");
}

__global__ void __launch_bounds__(TPB)
lightgcn_spmm_kernel(const int4*   __restrict__ rows4,
                     const int4*   __restrict__ cols4,
                     const float4* __restrict__ vals4,
                     const float4* __restrict__ x4,      // [N_NODES * 8]
                     float*        __restrict__ out,     // [N_NODES * 32]
                     int n_edges)
{
    int tid  = blockIdx.x * TPB + threadIdx.x;
    int warp = tid >> 5;
    int lane = threadIdx.x & 31;
    int q    = lane & 7;
    int sub  = lane >> 3;

    float* outq = out + q * 4;                 // hoist quarter offset
    int    g    = warp * (EPW / 4) + sub;      // group of 4 consecutive edges
    int    base = g * 4;

    if (base + 3 < n_edges) {
        // ---- fast path: whole int4 group valid ----
        int4   r = __ldg(&rows4[g]);
        int4   c = __ldg(&cols4[g]);
        float4 v = __ldg(&vals4[g]);

        int   ra[EPT] = { r.x, r.y, r.z, r.w };
        int   ca[EPT] = { c.x, c.y, c.z, c.w };
        float va[EPT] = { v.x, v.y, v.z, v.w };

        float4 xv[EPT];
        #pragma unroll
        for (int i = 0; i < EPT; i++)
            xv[i] = __ldg(&x4[ca[i] * QPE + q]);

        #pragma unroll
        for (int i = 0; i < EPT; i++) {
            float4 m;
            m.x = xv[i].x * va[i];
            m.y = xv[i].y * va[i];
            m.z = xv[i].z * va[i];
            m.w = xv[i].w * va[i];
            red_add_v4(outq + (size_t)ra[i] * DIM, m);
        }
    } else {
        // ---- tail path: per-edge scalar ----
        const int*   rows = (const int*)  rows4;
        const int*   cols = (const int*)  cols4;
        const float* vals = (const float*)vals4;
        #pragma unroll
        for (int i = 0; i < EPT; i++) {
            int e = base + i;
            if (e < n_edges) {
                int   rr = __ldg(&rows[e]);
                int   cc = __ldg(&cols[e]);
                float vv = __ldg(&vals[e]);
                float4 xv = __ldg(&x4[cc * QPE + q]);
                float4 m;
                m.x = xv.x * vv;
                m.y = xv.y * vv;
                m.z = xv.z * vv;
                m.w = xv.w * vv;
                red_add_v4(outq + (size_t)rr * DIM, m);
            }
        }
    }
}

extern "C" void kernel_launch(void* const* d_in, const int* in_sizes, int n_in,
                              void* d_out, int out_size)
{
    const int4*   rows4 = (const int4*)  d_in[0];  // A_rows [E]
    const int4*   cols4 = (const int4*)  d_in[1];  // A_cols [E]
    const float4* vals4 = (const float4*)d_in[2];  // A_vals [E]
    const float4* x4    = (const float4*)d_in[3];  // x [N, 32] as float4[N*8]
    float*        out   = (float*)d_out;

    int n_edges = in_sizes[0];

    // Output is poisoned to 0xAA by the harness; reductions need zeros.
    cudaMemsetAsync(d_out, 0, (size_t)out_size * sizeof(float), 0);

    int n_warps  = (n_edges + EPW - 1) / EPW;
    int n_thread = n_warps * 32;
    int blocks   = (n_thread + TPB - 1) / TPB;
    lightgcn_spmm_kernel<<<blocks, TPB>>>(rows4, cols4, vals4, x4, out, n_edges);
}